// round 14
// baseline (speedup 1.0000x reference)
#include <cuda_runtime.h>
#include <cuda_fp16.h>
#include <math.h>
#include <stdint.h>

#define Bq    2
#define Tq    2048
#define BT    4096
#define Dq    512
#define Sq    256
#define Lq    4
#define DFFq  1368
#define Vq    32000
#define EPSq  1e-5f
#define NCHUNK 64
#define CLEN   32    // Tq / NCHUNK

// ---------------- fp32 scratch ----------------
__device__ __align__(128) float g_h [(size_t)BT * Dq];    // residual stream
__device__ __align__(128) float g_bu[(size_t)BT * Sq];    // Bu (fp32, scan in place)
__device__ __align__(128) float g_carry[NCHUNK * Bq * Sq]; // [chunk][b][s]

// ---------------- fp16 scratch ----------------
__device__ __align__(128) __half g_lnh[(size_t)BT * Dq];   // LN output (A operand)
__device__ __align__(128) __half g_buh[(size_t)BT * Sq];   // scanned h (A operand)
__device__ __align__(128) __half g_ffh[(size_t)BT * DFFq]; // gated product (A operand)

// ---------------- fp16 weight arena ----------------
#define CNT_HEAD (Vq * Dq)
#define CNT_BW   (Lq * Sq * Dq)
#define CNT_W    (Lq * DFFq * Dq)
#define OFF_HEAD 0
#define OFF_BW   (OFF_HEAD + CNT_HEAD)
#define OFF_CW   (OFF_BW + CNT_BW)
#define OFF_W12  (OFF_CW + CNT_BW)         // interleaved w1/w2: 2*CNT_W
#define OFF_W3   (OFF_W12 + 2 * CNT_W)
#define GW_TOTAL (OFF_W3 + CNT_W)
__device__ __align__(128) __half g_w[(size_t)GW_TOTAL];

// ---------------- helpers ----------------
__device__ __forceinline__ uint32_t pack_h2(float x, float y) {
    __half2 h = __floats2half2_rn(x, y);
    return *(uint32_t*)&h;
}
__device__ __forceinline__ void ldm_x4(uint32_t* r, uint32_t addr) {
    asm volatile("ldmatrix.sync.aligned.m8n8.x4.shared.b16 {%0,%1,%2,%3}, [%4];"
                 : "=r"(r[0]), "=r"(r[1]), "=r"(r[2]), "=r"(r[3]) : "r"(addr));
}
__device__ __forceinline__ void mma_f16(float* c, const uint32_t* a, uint32_t b0, uint32_t b1) {
    asm volatile(
        "mma.sync.aligned.m16n8k16.row.col.f32.f16.f16.f32 "
        "{%0,%1,%2,%3}, {%4,%5,%6,%7}, {%8,%9}, {%0,%1,%2,%3};"
        : "+f"(c[0]), "+f"(c[1]), "+f"(c[2]), "+f"(c[3])
        : "r"(a[0]), "r"(a[1]), "r"(a[2]), "r"(a[3]), "r"(b0), "r"(b1));
}
__device__ __forceinline__ void cp16(uint32_t dst, const void* src, int sz) {
    asm volatile("cp.async.cg.shared.global [%0], [%1], 16, %2;"
                 :: "r"(dst), "l"(src), "r"(sz) : "memory");
}
#define CP_COMMIT() asm volatile("cp.async.commit_group;" ::: "memory")
#define CP_WAIT1()  asm volatile("cp.async.wait_group 1;" ::: "memory")
#define CP_WAIT0()  asm volatile("cp.async.wait_group 0;" ::: "memory")

// ---------------- weight converts (fp32 -> fp16) ----------------
__global__ void k_cvt(const float* __restrict__ s, __half* __restrict__ d, int n8)
{
    const int i = blockIdx.x * blockDim.x + threadIdx.x;
    if (i >= n8) return;
    float4 a = ((const float4*)s)[2 * i];
    float4 b = ((const float4*)s)[2 * i + 1];
    uint4 o;
    o.x = pack_h2(a.x, a.y); o.y = pack_h2(a.z, a.w);
    o.z = pack_h2(b.x, b.y); o.w = pack_h2(b.z, b.w);
    ((uint4*)d)[i] = o;
}

// interleave w1/w2 rows per layer: dst row (l, 2f) = w1[l,f], (l, 2f+1) = w2[l,f]
__global__ void k_cvt2(const float* __restrict__ w1, const float* __restrict__ w2,
                       __half* __restrict__ d, int n8)
{
    const int i = blockIdx.x * blockDim.x + threadIdx.x;
    if (i >= n8) return;
    const int fg  = i >> 6;
    const int off = (i & 63) * 8;
    const int l   = fg / DFFq;
    const int f   = fg - l * DFFq;
    const float4* s1 = (const float4*)(w1 + (size_t)fg * Dq + off);
    const float4* s2 = (const float4*)(w2 + (size_t)fg * Dq + off);
    __half* dst = d + ((size_t)l * 2 * DFFq + 2 * f) * Dq + off;
    float4 a = s1[0], b = s1[1];
    uint4 o;
    o.x = pack_h2(a.x, a.y); o.y = pack_h2(a.z, a.w);
    o.z = pack_h2(b.x, b.y); o.w = pack_h2(b.z, b.w);
    *(uint4*)dst = o;
    a = s2[0]; b = s2[1];
    o.x = pack_h2(a.x, a.y); o.y = pack_h2(a.z, a.w);
    o.z = pack_h2(b.x, b.y); o.w = pack_h2(b.z, b.w);
    *(uint4*)(dst + Dq) = o;
}

// ---------------- LN core (128 threads, one row of 512) ----------------
__device__ __forceinline__ void ln_row(const float4 v, const float* w, const float* b,
                                       __half* out_row, int c)
{
    float s  = v.x + v.y + v.z + v.w;
    float ss = v.x*v.x + v.y*v.y + v.z*v.z + v.w*v.w;
#pragma unroll
    for (int o = 16; o > 0; o >>= 1) {
        s  += __shfl_xor_sync(0xffffffffu, s,  o);
        ss += __shfl_xor_sync(0xffffffffu, ss, o);
    }
    __shared__ float sm[10];
    const int wid = c >> 5;
    if ((c & 31) == 0) { sm[wid] = s; sm[4 + wid] = ss; }
    __syncthreads();
    if (c == 0) {
        float S1 = sm[0] + sm[1] + sm[2] + sm[3];
        float S2 = sm[4] + sm[5] + sm[6] + sm[7];
        float mu  = S1 * (1.0f / Dq);
        float var = S2 * (1.0f / Dq) - mu * mu;
        sm[8] = mu;
        sm[9] = rsqrtf(var + EPSq);
    }
    __syncthreads();
    const float mu = sm[8], rs = sm[9];
    const float4 wv = ((const float4*)w)[c];
    const float4 bv = ((const float4*)b)[c];
    uint2 o;
    o.x = pack_h2((v.x - mu) * rs * wv.x + bv.x, (v.y - mu) * rs * wv.y + bv.y);
    o.y = pack_h2((v.z - mu) * rs * wv.z + bv.z, (v.w - mu) * rs * wv.w + bv.w);
    ((uint2*)out_row)[c] = o;
}

// ---------------- fused embedding + first LN ----------------
__global__ void k_embed_ln(const int* __restrict__ x, const float* __restrict__ emb,
                           const float* __restrict__ pos,
                           const float* __restrict__ w, const float* __restrict__ b)
{
    const int row = blockIdx.x;
    const int t   = row & (Tq - 1);
    const int tok = x[row];
    const int c   = threadIdx.x;
    const float4 e = ((const float4*)(emb + (size_t)tok * Dq))[c];
    const float4 p = ((const float4*)(pos + (size_t)t * Dq))[c];
    const float4 v = make_float4(e.x + p.x, e.y + p.y, e.z + p.z, e.w + p.w);
    ((float4*)(g_h + (size_t)row * Dq))[c] = v;
    ln_row(v, w, b, g_lnh + (size_t)row * Dq, c);
}

// ---------------- layernorm: fp32 in -> fp16 out ----------------
__global__ void k_ln(const float* __restrict__ in, __half* __restrict__ out,
                     const float* __restrict__ w, const float* __restrict__ b)
{
    const int row = blockIdx.x;
    const int c = threadIdx.x;
    const float4 v = ((const float4*)(in + (size_t)row * Dq))[c];
    ln_row(v, w, b, out + (size_t)row * Dq, c);
}

// =================== fp16 mma GEMM: C = A[M,K]*B[N,K]^T (half inputs) ===========
// CTA tile MT x NT, BK=64, 3-stage cp.async, 256 threads = 8 warps (2m x 4n).
// Warp tile (MT/2) x (NT/4). Single barrier per chunk.
// MODE 0: C = acc                              (fp32 out)
// MODE 1: fused SwiGLU, interleaved N=2*DFF:   Ch[m][n>>1] = silu(g)*v
// MODE 2: C = C + acc + aux1[n]*aux2h[m,n]     (SSM residual)
// MODE 3: C = C + acc                          (FFN residual)
// MODE 4: C = acc + aux1[n]                    (head bias)
template<int MODE, int MT, int NT>
__global__ void __launch_bounds__(256, (MT * NT > 16384) ? 1 : 2)
k_mma(const __half* __restrict__ A, const __half* __restrict__ Bm,
      float* __restrict__ C, __half* __restrict__ Ch, int M, int N, int K,
      const float* __restrict__ aux1, const __half* __restrict__ aux2)
{
    constexpr int MI   = MT / 32;        // A staging iters / m16 frags per warp
    constexpr int NI   = NT / 32;        // n8 frags per warp
    constexpr int WMR  = MT / 2;         // warp m rows
    constexpr int WNR  = NT / 4;         // warp n cols
    constexpr uint32_t ASTG = (uint32_t)MT * 128;
    constexpr uint32_t BSTG = (uint32_t)NT * 128;
    constexpr uint32_t BOFF = 3 * ASTG;

    extern __shared__ char smem[];
    const uint32_t sb = (uint32_t)__cvta_generic_to_shared(smem);

    const int tid  = threadIdx.x;
    const int wid  = tid >> 5;
    const int lane = tid & 31;
    const int gid  = lane >> 2;
    const int tig  = lane & 3;
    const int hi   = lane >> 4;
    const int lrow = lane & 15;
    const int rswz = lrow & 7;
    const int wm   = wid & 1;
    const int wn   = wid >> 1;
    const int bm   = blockIdx.x * MT;
    const int bn   = blockIdx.y * NT;

    const int r0  = tid >> 3;
    const int c16 = tid & 7;
    const uint32_t swz16 = (uint32_t)((c16 ^ (r0 & 7)) * 16);
    const __half* Asrc = A  + (size_t)(bm + r0) * K + c16 * 8;
    const __half* Bsrc = Bm + (size_t)(bn + r0) * K + c16 * 8;

    float acc[MI][NI][4];
#pragma unroll
    for (int i = 0; i < MI; i++)
#pragma unroll
        for (int j = 0; j < NI; j++)
#pragma unroll
            for (int q = 0; q < 4; q++) acc[i][j][q] = 0.f;

    const int nk = (K + 63) >> 6;

    auto issue = [&](int kc) {
        const uint32_t sta = (uint32_t)(kc % 3) * ASTG;
        const uint32_t stb = BOFF + (uint32_t)(kc % 3) * BSTG;
        const int k0 = kc << 6;
        const int ksz = (k0 + c16 * 8 + 8 <= K) ? 16 : 0;
#pragma unroll
        for (int i = 0; i < MI; i++) {
            const uint32_t dof = (uint32_t)((i * 32 + r0) * 128) + swz16;
            cp16(sb + sta + dof, Asrc + (size_t)(i * 32) * K + k0, ksz);
        }
#pragma unroll
        for (int i = 0; i < NI; i++) {
            const uint32_t dof = (uint32_t)((i * 32 + r0) * 128) + swz16;
            const int bsz = ((bn + i * 32 + r0) < N) ? ksz : 0;
            cp16(sb + stb + dof, Bsrc + (size_t)(i * 32) * K + k0, bsz);
        }
        CP_COMMIT();
    };

    issue(0);
    issue(1);

#pragma unroll 1
    for (int kch = 0; kch < nk; kch++) {
        CP_WAIT1();
        __syncthreads();            // single barrier per chunk
        if (kch + 2 < nk) issue(kch + 2);

        const uint32_t arow = sb + (uint32_t)(kch % 3) * ASTG
                              + (uint32_t)((wm * WMR + lrow) * 128);
        const uint32_t brow = sb + BOFF + (uint32_t)(kch % 3) * BSTG
                              + (uint32_t)((wn * WNR + lrow) * 128);
#pragma unroll
        for (int ks = 0; ks < 4; ks++) {
            const uint32_t csw = (uint32_t)(((ks * 2 + hi) ^ rswz) * 16);
            uint32_t afr[MI][4];
#pragma unroll
            for (int mi = 0; mi < MI; mi++)
                ldm_x4(afr[mi], arow + (uint32_t)(mi * 16 * 128) + csw);
            uint32_t bfr[NI / 2][4];
#pragma unroll
            for (int nj = 0; nj < NI / 2; nj++)
                ldm_x4(bfr[nj], brow + (uint32_t)(nj * 16 * 128) + csw);
#pragma unroll
            for (int mi = 0; mi < MI; mi++)
#pragma unroll
                for (int ni = 0; ni < NI; ni++) {
                    const int nj = ni >> 1, h = ni & 1;
                    mma_f16(acc[mi][ni], afr[mi], bfr[nj][h], bfr[nj][h + 2]);
                }
        }
    }
    CP_WAIT0();

    // ---- epilogue ----
#pragma unroll
    for (int mi = 0; mi < MI; mi++) {
        const int r0m = bm + wm * WMR + mi * 16 + gid;
#pragma unroll
        for (int half = 0; half < 2; half++) {
            const int m = r0m + half * 8;
            const size_t rowoff = (size_t)m * N;
#pragma unroll
            for (int ni = 0; ni < NI; ni++) {
                const int n0 = bn + wn * WNR + ni * 8;
                if (n0 >= N) continue;
                const int n = n0 + tig * 2;
                float2 rv;
                rv.x = acc[mi][ni][half * 2 + 0];
                rv.y = acc[mi][ni][half * 2 + 1];
                if (MODE == 0) {
                    *(float2*)(C + rowoff + n) = rv;
                } else if (MODE == 1) {
                    const int f = n >> 1;
                    float r = rv.y * rv.x / (1.f + __expf(-rv.x));
                    Ch[(size_t)m * DFFq + f] = __float2half_rn(r);
                } else if (MODE == 2) {
                    float2* cp = (float2*)(C + rowoff + n);
                    float2 c  = *cp;
                    float2 dp = *(const float2*)(aux1 + n);
                    float2 u  = __half22float2(*(const __half2*)(aux2 + rowoff + n));
                    rv.x += c.x + dp.x * u.x;
                    rv.y += c.y + dp.y * u.y;
                    *cp = rv;
                } else if (MODE == 3) {
                    float2* cp = (float2*)(C + rowoff + n);
                    float2 c = *cp;
                    rv.x += c.x; rv.y += c.y;
                    *cp = rv;
                } else {
                    float2 bb = *(const float2*)(aux1 + n);
                    rv.x += bb.x; rv.y += bb.y;
                    *(float2*)(C + rowoff + n) = rv;
                }
            }
        }
    }
}

#define SMEM64   73728    // MT=64,  NT=128
#define SMEM128  98304    // MT=128, NT=128
#define SMEM256 147456    // MT=128, NT=256

// ---------------- SSM scan phase 1: local chunk scans + carries ----------------
__global__ void k_scan1(const float* __restrict__ loglam)
{
    const int idx   = blockIdx.x * blockDim.x + threadIdx.x;
    const int s     = idx & (Sq - 1);
    const int b     = (idx >> 8) & 1;
    const int chunk = idx >> 9;
    const float lam = 1.f / (1.f + expf(-loglam[s]));
    float* p = g_bu + ((size_t)(b * Tq + chunk * CLEN)) * Sq + s;
    float h = 0.f;
    float buf[4];
#pragma unroll
    for (int j = 0; j < 4; j++) buf[j] = p[(size_t)j * Sq];
#pragma unroll
    for (int j0 = 0; j0 < CLEN; j0 += 4) {
        float c0 = buf[0], c1 = buf[1], c2 = buf[2], c3 = buf[3];
        if (j0 + 4 < CLEN) {
#pragma unroll
            for (int j = 0; j < 4; j++) buf[j] = p[(size_t)(j0 + 4 + j) * Sq];
        }
        h = fmaf(lam, h, c0); p[(size_t)(j0 + 0) * Sq] = h;
        h = fmaf(lam, h, c1); p[(size_t)(j0 + 1) * Sq] = h;
        h = fmaf(lam, h, c2); p[(size_t)(j0 + 2) * Sq] = h;
        h = fmaf(lam, h, c3); p[(size_t)(j0 + 3) * Sq] = h;
    }
    g_carry[(size_t)chunk * (Bq * Sq) + b * Sq + s] = h;      // [chunk][b][s]
}

// ---------------- scan phase 2+3 fused: local carry-prefix, fixup, half out ----
__global__ void k_scan23(const float* __restrict__ loglam)
{
    const int idx   = blockIdx.x * blockDim.x + threadIdx.x;
    const int s     = idx & (Sq - 1);
    const int b     = (idx >> 8) & 1;
    const int chunk = idx >> 9;                               // warp-uniform
    const float lam = 1.f / (1.f + expf(-loglam[s]));
    float lp = lam;
#pragma unroll
    for (int i = 0; i < 5; i++) lp *= lp;                     // lam^32
    const float* cb = g_carry + b * Sq + s;
    float H = 0.f;
    for (int c = 0; c < chunk; c++)
        H = fmaf(lp, H, cb[(size_t)c * (Bq * Sq)]);
    const size_t base = ((size_t)(b * Tq + chunk * CLEN)) * Sq + s;
    const float* p = g_bu + base;
    __half* ph = g_buh + base;
    float f = lam;
#pragma unroll
    for (int j0 = 0; j0 < CLEN; j0 += 8) {
        float v[8];
#pragma unroll
        for (int u = 0; u < 8; u++) v[u] = p[(size_t)(j0 + u) * Sq];
#pragma unroll
        for (int u = 0; u < 8; u++) { v[u] += f * H; f *= lam; }
#pragma unroll
        for (int u = 0; u < 8; u++) ph[(size_t)(j0 + u) * Sq] = __float2half_rn(v[u]);
    }
}

// ---------------- orchestration ----------------
extern "C" void kernel_launch(void* const* d_in, const int* in_sizes, int n_in,
                              void* d_out, int out_size)
{
    const int*   x      = (const int*)  d_in[0];
    const float* emb    = (const float*)d_in[1];
    const float* pos    = (const float*)d_in[2];
    const float* loglam = (const float*)d_in[3];
    const float* Bw     = (const float*)d_in[4];
    const float* Cw     = (const float*)d_in[5];
    const float* Dp     = (const float*)d_in[6];
    const float* n1w    = (const float*)d_in[7];
    const float* n1b    = (const float*)d_in[8];
    const float* n2w    = (const float*)d_in[9];
    const float* n2b    = (const float*)d_in[10];
    const float* w1     = (const float*)d_in[11];
    const float* w2     = (const float*)d_in[12];
    const float* w3     = (const float*)d_in[13];
    const float* now    = (const float*)d_in[14];
    const float* nob    = (const float*)d_in[15];
    const float* headW  = (const float*)d_in[16];
    const float* headb  = (const float*)d_in[17];
    float* out = (float*)d_out;

    void *ph, *pb, *plh, *pbh, *pfh, *pw;
    cudaGetSymbolAddress(&ph,  g_h);
    cudaGetSymbolAddress(&pb,  g_bu);
    cudaGetSymbolAddress(&plh, g_lnh);
    cudaGetSymbolAddress(&pbh, g_buh);
    cudaGetSymbolAddress(&pfh, g_ffh);
    cudaGetSymbolAddress(&pw,  g_w);
    float*  h   = (float*)ph;
    float*  bu  = (float*)pb;
    __half* lnh = (__half*)plh;
    __half* buh = (__half*)pbh;
    __half* ffh = (__half*)pfh;
    __half* gw  = (__half*)pw;

    cudaFuncSetAttribute((const void*)k_mma<0,64,128>,  cudaFuncAttributeMaxDynamicSharedMemorySize, SMEM64);
    cudaFuncSetAttribute((const void*)k_mma<2,64,128>,  cudaFuncAttributeMaxDynamicSharedMemorySize, SMEM64);
    cudaFuncSetAttribute((const void*)k_mma<3,64,128>,  cudaFuncAttributeMaxDynamicSharedMemorySize, SMEM64);
    cudaFuncSetAttribute((const void*)k_mma<1,128,128>, cudaFuncAttributeMaxDynamicSharedMemorySize, SMEM128);
    cudaFuncSetAttribute((const void*)k_mma<4,128,256>, cudaFuncAttributeMaxDynamicSharedMemorySize, SMEM256);

    // ---- weight conversion (once per launch) ----
    k_cvt <<<8000, 256>>>(headW, gw + OFF_HEAD, CNT_HEAD / 8);
    k_cvt <<<256,  256>>>(Bw,    gw + OFF_BW,   CNT_BW / 8);
    k_cvt <<<256,  256>>>(Cw,    gw + OFF_CW,   CNT_BW / 8);
    k_cvt2<<<1368, 256>>>(w1, w2, gw + OFF_W12, CNT_W / 8);
    k_cvt <<<1368, 256>>>(w3,    gw + OFF_W3,   CNT_W / 8);

    const dim3 gBu(BT / 64, Sq / 128);                    // 64 x 2
    const dim3 gC (BT / 64, Dq / 128);                    // 64 x 4
    const dim3 gW12(BT / 128, (2 * DFFq + 127) / 128);    // 32 x 22
    const dim3 gW3(BT / 64, Dq / 128);                    // 64 x 4
    const dim3 gHd(BT / 128, Vq / 256);                   // 32 x 125

    // fused embedding + layer-0 first LN
    k_embed_ln<<<BT, 128>>>(x, emb, pos, n1w, n1b);

    const int lBw = Sq * Dq;
    for (int l = 0; l < Lq; l++) {
        // ---- SSM block ----
        if (l > 0) k_ln<<<BT, 128>>>(h, lnh, n1w + l * Dq, n1b + l * Dq);
        k_mma<0,64,128><<<gBu, 256, SMEM64>>>(lnh, gw + OFF_BW + (size_t)l * lBw,
                                              bu, nullptr, BT, Sq, Dq, nullptr, nullptr);
        k_scan1 <<<128, 256>>>(loglam + l * Sq);
        k_scan23<<<128, 256>>>(loglam + l * Sq);
        k_mma<2,64,128><<<gC, 256, SMEM64>>>(buh, gw + OFF_CW + (size_t)l * lBw,
                                             h, nullptr, BT, Dq, Sq, Dp + l * Dq, lnh);
        // ---- SwiGLU block (fused w1+w2 interleaved) ----
        k_ln<<<BT, 128>>>(h, lnh, n2w + l * Dq, n2b + l * Dq);
        k_mma<1,128,128><<<gW12, 256, SMEM128>>>(lnh, gw + OFF_W12 + (size_t)l * 2 * DFFq * Dq,
                                                 nullptr, ffh, BT, 2 * DFFq, Dq, nullptr, nullptr);
        k_mma<3,64,128><<<gW3, 256, SMEM64>>>(ffh, gw + OFF_W3 + (size_t)l * DFFq * Dq,
                                              h, nullptr, BT, Dq, DFFq, nullptr, nullptr);
    }

    // ---- head (128x256 tiles) ----
    k_ln<<<BT, 128>>>(h, lnh, now, nob);
    k_mma<4,128,256><<<gHd, 256, SMEM256>>>(lnh, gw + OFF_HEAD,
                                            out, nullptr, BT, Vq, Dq, headb, nullptr);
}

// round 16
// speedup vs baseline: 1.0579x; 1.0579x over previous
#include <cuda_runtime.h>
#include <cuda_fp16.h>
#include <math.h>
#include <stdint.h>

#define Bq    2
#define Tq    2048
#define BT    4096
#define Dq    512
#define Sq    256
#define Lq    4
#define DFFq  1368
#define Vq    32000
#define EPSq  1e-5f
#define NCHUNK 64
#define CLEN   32    // Tq / NCHUNK

// ---------------- fp32 scratch ----------------
__device__ __align__(128) float g_h [(size_t)BT * Dq];    // residual stream
__device__ __align__(128) float g_bu[(size_t)BT * Sq];    // Bu (fp32, scan in place)
__device__ __align__(128) float g_carry[NCHUNK * Bq * Sq]; // [chunk][b][s]

// ---------------- fp16 scratch ----------------
__device__ __align__(128) __half g_lnh[(size_t)BT * Dq];   // LN output (A operand)
__device__ __align__(128) __half g_buh[(size_t)BT * Sq];   // scanned h (A operand)
__device__ __align__(128) __half g_ffh[(size_t)BT * DFFq]; // gated product (A operand)

// ---------------- fp16 weight arena ----------------
#define CNT_HEAD (Vq * Dq)
#define CNT_BW   (Lq * Sq * Dq)
#define CNT_W    (Lq * DFFq * Dq)
#define OFF_HEAD 0
#define OFF_BW   (OFF_HEAD + CNT_HEAD)
#define OFF_CW   (OFF_BW + CNT_BW)
#define OFF_W12  (OFF_CW + CNT_BW)         // interleaved w1/w2: 2*CNT_W
#define OFF_W3   (OFF_W12 + 2 * CNT_W)
#define GW_TOTAL (OFF_W3 + CNT_W)
__device__ __align__(128) __half g_w[(size_t)GW_TOTAL];

// ---------------- helpers ----------------
__device__ __forceinline__ uint32_t pack_h2(float x, float y) {
    __half2 h = __floats2half2_rn(x, y);
    return *(uint32_t*)&h;
}
__device__ __forceinline__ void ldm_x4(uint32_t* r, uint32_t addr) {
    asm volatile("ldmatrix.sync.aligned.m8n8.x4.shared.b16 {%0,%1,%2,%3}, [%4];"
                 : "=r"(r[0]), "=r"(r[1]), "=r"(r[2]), "=r"(r[3]) : "r"(addr));
}
__device__ __forceinline__ void mma_f16(float* c, const uint32_t* a, uint32_t b0, uint32_t b1) {
    asm volatile(
        "mma.sync.aligned.m16n8k16.row.col.f32.f16.f16.f32 "
        "{%0,%1,%2,%3}, {%4,%5,%6,%7}, {%8,%9}, {%0,%1,%2,%3};"
        : "+f"(c[0]), "+f"(c[1]), "+f"(c[2]), "+f"(c[3])
        : "r"(a[0]), "r"(a[1]), "r"(a[2]), "r"(a[3]), "r"(b0), "r"(b1));
}
__device__ __forceinline__ void cp16(uint32_t dst, const void* src, int sz) {
    asm volatile("cp.async.cg.shared.global [%0], [%1], 16, %2;"
                 :: "r"(dst), "l"(src), "r"(sz) : "memory");
}
#define CP_COMMIT() asm volatile("cp.async.commit_group;" ::: "memory")
#define CP_WAIT1()  asm volatile("cp.async.wait_group 1;" ::: "memory")
#define CP_WAIT0()  asm volatile("cp.async.wait_group 0;" ::: "memory")

// ---------------- weight converts (fp32 -> fp16) ----------------
__global__ void k_cvt(const float* __restrict__ s, __half* __restrict__ d, int n8)
{
    const int i = blockIdx.x * blockDim.x + threadIdx.x;
    if (i >= n8) return;
    float4 a = ((const float4*)s)[2 * i];
    float4 b = ((const float4*)s)[2 * i + 1];
    uint4 o;
    o.x = pack_h2(a.x, a.y); o.y = pack_h2(a.z, a.w);
    o.z = pack_h2(b.x, b.y); o.w = pack_h2(b.z, b.w);
    ((uint4*)d)[i] = o;
}

// interleave w1/w2 rows per layer: dst row (l, 2f) = w1[l,f], (l, 2f+1) = w2[l,f]
__global__ void k_cvt2(const float* __restrict__ w1, const float* __restrict__ w2,
                       __half* __restrict__ d, int n8)
{
    const int i = blockIdx.x * blockDim.x + threadIdx.x;
    if (i >= n8) return;
    const int fg  = i >> 6;
    const int off = (i & 63) * 8;
    const int l   = fg / DFFq;
    const int f   = fg - l * DFFq;
    const float4* s1 = (const float4*)(w1 + (size_t)fg * Dq + off);
    const float4* s2 = (const float4*)(w2 + (size_t)fg * Dq + off);
    __half* dst = d + ((size_t)l * 2 * DFFq + 2 * f) * Dq + off;
    float4 a = s1[0], b = s1[1];
    uint4 o;
    o.x = pack_h2(a.x, a.y); o.y = pack_h2(a.z, a.w);
    o.z = pack_h2(b.x, b.y); o.w = pack_h2(b.z, b.w);
    *(uint4*)dst = o;
    a = s2[0]; b = s2[1];
    o.x = pack_h2(a.x, a.y); o.y = pack_h2(a.z, a.w);
    o.z = pack_h2(b.x, b.y); o.w = pack_h2(b.z, b.w);
    *(uint4*)(dst + Dq) = o;
}

// ---------------- LN core (128 threads, one row of 512) ----------------
__device__ __forceinline__ void ln_row(const float4 v, const float* w, const float* b,
                                       __half* out_row, int c)
{
    float s  = v.x + v.y + v.z + v.w;
    float ss = v.x*v.x + v.y*v.y + v.z*v.z + v.w*v.w;
#pragma unroll
    for (int o = 16; o > 0; o >>= 1) {
        s  += __shfl_xor_sync(0xffffffffu, s,  o);
        ss += __shfl_xor_sync(0xffffffffu, ss, o);
    }
    __shared__ float sm[10];
    const int wid = c >> 5;
    if ((c & 31) == 0) { sm[wid] = s; sm[4 + wid] = ss; }
    __syncthreads();
    if (c == 0) {
        float S1 = sm[0] + sm[1] + sm[2] + sm[3];
        float S2 = sm[4] + sm[5] + sm[6] + sm[7];
        float mu  = S1 * (1.0f / Dq);
        float var = S2 * (1.0f / Dq) - mu * mu;
        sm[8] = mu;
        sm[9] = rsqrtf(var + EPSq);
    }
    __syncthreads();
    const float mu = sm[8], rs = sm[9];
    const float4 wv = ((const float4*)w)[c];
    const float4 bv = ((const float4*)b)[c];
    uint2 o;
    o.x = pack_h2((v.x - mu) * rs * wv.x + bv.x, (v.y - mu) * rs * wv.y + bv.y);
    o.y = pack_h2((v.z - mu) * rs * wv.z + bv.z, (v.w - mu) * rs * wv.w + bv.w);
    ((uint2*)out_row)[c] = o;
}

// ---------------- fused embedding + first LN ----------------
__global__ void k_embed_ln(const int* __restrict__ x, const float* __restrict__ emb,
                           const float* __restrict__ pos,
                           const float* __restrict__ w, const float* __restrict__ b)
{
    const int row = blockIdx.x;
    const int t   = row & (Tq - 1);
    const int tok = x[row];
    const int c   = threadIdx.x;
    const float4 e = ((const float4*)(emb + (size_t)tok * Dq))[c];
    const float4 p = ((const float4*)(pos + (size_t)t * Dq))[c];
    const float4 v = make_float4(e.x + p.x, e.y + p.y, e.z + p.z, e.w + p.w);
    ((float4*)(g_h + (size_t)row * Dq))[c] = v;
    ln_row(v, w, b, g_lnh + (size_t)row * Dq, c);
}

// ---------------- layernorm: fp32 in -> fp16 out ----------------
__global__ void k_ln(const float* __restrict__ in, __half* __restrict__ out,
                     const float* __restrict__ w, const float* __restrict__ b)
{
    const int row = blockIdx.x;
    const int c = threadIdx.x;
    const float4 v = ((const float4*)(in + (size_t)row * Dq))[c];
    ln_row(v, w, b, out + (size_t)row * Dq, c);
}

// =================== fp16 mma GEMM: C = A[M,K]*B[N,K]^T (half inputs) ===========
// CTA tile MT x NT, BK=64, 3-stage cp.async, 256 threads = 8 warps (2m x 4n).
// Warp tile (MT/2) x (NT/4). Single barrier per chunk.
// TAIL FIX: last iteration must drain ALL cp.async groups (wait_group 0) —
// wait_group 1 is vacuous when the final chunk's group is the only one pending.
// MODE 0: C = acc                              (fp32 out)
// MODE 1: fused SwiGLU, interleaved N=2*DFF:   Ch[m][n>>1] = silu(g)*v
// MODE 2: C = C + acc + aux1[n]*aux2h[m,n]     (SSM residual)
// MODE 3: C = C + acc                          (FFN residual)
// MODE 4: C = acc + aux1[n]                    (head bias)
template<int MODE, int MT, int NT>
__global__ void __launch_bounds__(256, 2)
k_mma(const __half* __restrict__ A, const __half* __restrict__ Bm,
      float* __restrict__ C, __half* __restrict__ Ch, int M, int N, int K,
      const float* __restrict__ aux1, const __half* __restrict__ aux2)
{
    constexpr int MI   = MT / 32;        // A staging iters / m16 frags per warp
    constexpr int NI   = NT / 32;        // n8 frags per warp
    constexpr int WMR  = MT / 2;         // warp m rows
    constexpr int WNR  = NT / 4;         // warp n cols
    constexpr uint32_t ASTG = (uint32_t)MT * 128;
    constexpr uint32_t BSTG = (uint32_t)NT * 128;
    constexpr uint32_t BOFF = 3 * ASTG;

    extern __shared__ char smem[];
    const uint32_t sb = (uint32_t)__cvta_generic_to_shared(smem);

    const int tid  = threadIdx.x;
    const int wid  = tid >> 5;
    const int lane = tid & 31;
    const int gid  = lane >> 2;
    const int tig  = lane & 3;
    const int hi   = lane >> 4;
    const int lrow = lane & 15;
    const int rswz = lrow & 7;
    const int wm   = wid & 1;
    const int wn   = wid >> 1;
    const int bm   = blockIdx.x * MT;
    const int bn   = blockIdx.y * NT;

    const int r0  = tid >> 3;
    const int c16 = tid & 7;
    const uint32_t swz16 = (uint32_t)((c16 ^ (r0 & 7)) * 16);
    const __half* Asrc = A  + (size_t)(bm + r0) * K + c16 * 8;
    const __half* Bsrc = Bm + (size_t)(bn + r0) * K + c16 * 8;

    float acc[MI][NI][4];
#pragma unroll
    for (int i = 0; i < MI; i++)
#pragma unroll
        for (int j = 0; j < NI; j++)
#pragma unroll
            for (int q = 0; q < 4; q++) acc[i][j][q] = 0.f;

    const int nk = (K + 63) >> 6;

    auto issue = [&](int kc) {
        const uint32_t sta = (uint32_t)(kc % 3) * ASTG;
        const uint32_t stb = BOFF + (uint32_t)(kc % 3) * BSTG;
        const int k0 = kc << 6;
        const int ksz = (k0 + c16 * 8 + 8 <= K) ? 16 : 0;
#pragma unroll
        for (int i = 0; i < MI; i++) {
            const uint32_t dof = (uint32_t)((i * 32 + r0) * 128) + swz16;
            cp16(sb + sta + dof, Asrc + (size_t)(i * 32) * K + k0, ksz);
        }
#pragma unroll
        for (int i = 0; i < NI; i++) {
            const uint32_t dof = (uint32_t)((i * 32 + r0) * 128) + swz16;
            const int bsz = ((bn + i * 32 + r0) < N) ? ksz : 0;
            cp16(sb + stb + dof, Bsrc + (size_t)(i * 32) * K + k0, bsz);
        }
        CP_COMMIT();
    };

    issue(0);
    issue(1);

#pragma unroll 1
    for (int kch = 0; kch < nk; kch++) {
        if (kch + 1 < nk) { CP_WAIT1(); } else { CP_WAIT0(); }   // tail fix
        __syncthreads();            // single barrier per chunk
        if (kch + 2 < nk) issue(kch + 2);

        const uint32_t arow = sb + (uint32_t)(kch % 3) * ASTG
                              + (uint32_t)((wm * WMR + lrow) * 128);
        const uint32_t brow = sb + BOFF + (uint32_t)(kch % 3) * BSTG
                              + (uint32_t)((wn * WNR + lrow) * 128);
#pragma unroll
        for (int ks = 0; ks < 4; ks++) {
            const uint32_t csw = (uint32_t)(((ks * 2 + hi) ^ rswz) * 16);
            uint32_t afr[MI][4];
#pragma unroll
            for (int mi = 0; mi < MI; mi++)
                ldm_x4(afr[mi], arow + (uint32_t)(mi * 16 * 128) + csw);
            uint32_t bfr[NI / 2][4];
#pragma unroll
            for (int nj = 0; nj < NI / 2; nj++)
                ldm_x4(bfr[nj], brow + (uint32_t)(nj * 16 * 128) + csw);
#pragma unroll
            for (int mi = 0; mi < MI; mi++)
#pragma unroll
                for (int ni = 0; ni < NI; ni++) {
                    const int nj = ni >> 1, h = ni & 1;
                    mma_f16(acc[mi][ni], afr[mi], bfr[nj][h], bfr[nj][h + 2]);
                }
        }
    }

    // ---- epilogue ----
#pragma unroll
    for (int mi = 0; mi < MI; mi++) {
        const int r0m = bm + wm * WMR + mi * 16 + gid;
#pragma unroll
        for (int half = 0; half < 2; half++) {
            const int m = r0m + half * 8;
            const size_t rowoff = (size_t)m * N;
#pragma unroll
            for (int ni = 0; ni < NI; ni++) {
                const int n0 = bn + wn * WNR + ni * 8;
                if (n0 >= N) continue;
                const int n = n0 + tig * 2;
                float2 rv;
                rv.x = acc[mi][ni][half * 2 + 0];
                rv.y = acc[mi][ni][half * 2 + 1];
                if (MODE == 0) {
                    *(float2*)(C + rowoff + n) = rv;
                } else if (MODE == 1) {
                    const int f = n >> 1;
                    float r = rv.y * rv.x / (1.f + __expf(-rv.x));
                    Ch[(size_t)m * DFFq + f] = __float2half_rn(r);
                } else if (MODE == 2) {
                    float2* cp = (float2*)(C + rowoff + n);
                    float2 c  = *cp;
                    float2 dp = *(const float2*)(aux1 + n);
                    float2 u  = __half22float2(*(const __half2*)(aux2 + rowoff + n));
                    rv.x += c.x + dp.x * u.x;
                    rv.y += c.y + dp.y * u.y;
                    *cp = rv;
                } else if (MODE == 3) {
                    float2* cp = (float2*)(C + rowoff + n);
                    float2 c = *cp;
                    rv.x += c.x; rv.y += c.y;
                    *cp = rv;
                } else {
                    float2 bb = *(const float2*)(aux1 + n);
                    rv.x += bb.x; rv.y += bb.y;
                    *(float2*)(C + rowoff + n) = rv;
                }
            }
        }
    }
}

#define SMEM6464 49152    // MT=64,  NT=64
#define SMEM64   73728    // MT=64,  NT=128
#define SMEM128  98304    // MT=128, NT=128

// ---------------- SSM scan phase 1: local chunk scans + carries ----------------
__global__ void k_scan1(const float* __restrict__ loglam)
{
    const int idx   = blockIdx.x * blockDim.x + threadIdx.x;
    const int s     = idx & (Sq - 1);
    const int b     = (idx >> 8) & 1;
    const int chunk = idx >> 9;
    const float lam = 1.f / (1.f + expf(-loglam[s]));
    float* p = g_bu + ((size_t)(b * Tq + chunk * CLEN)) * Sq + s;
    float h = 0.f;
    float buf[4];
#pragma unroll
    for (int j = 0; j < 4; j++) buf[j] = p[(size_t)j * Sq];
#pragma unroll
    for (int j0 = 0; j0 < CLEN; j0 += 4) {
        float c0 = buf[0], c1 = buf[1], c2 = buf[2], c3 = buf[3];
        if (j0 + 4 < CLEN) {
#pragma unroll
            for (int j = 0; j < 4; j++) buf[j] = p[(size_t)(j0 + 4 + j) * Sq];
        }
        h = fmaf(lam, h, c0); p[(size_t)(j0 + 0) * Sq] = h;
        h = fmaf(lam, h, c1); p[(size_t)(j0 + 1) * Sq] = h;
        h = fmaf(lam, h, c2); p[(size_t)(j0 + 2) * Sq] = h;
        h = fmaf(lam, h, c3); p[(size_t)(j0 + 3) * Sq] = h;
    }
    g_carry[(size_t)chunk * (Bq * Sq) + b * Sq + s] = h;      // [chunk][b][s]
}

// ---------------- scan phase 2+3 fused: local carry-prefix, fixup, half out ----
__global__ void k_scan23(const float* __restrict__ loglam)
{
    const int idx   = blockIdx.x * blockDim.x + threadIdx.x;
    const int s     = idx & (Sq - 1);
    const int b     = (idx >> 8) & 1;
    const int chunk = idx >> 9;                               // warp-uniform
    const float lam = 1.f / (1.f + expf(-loglam[s]));
    float lp = lam;
#pragma unroll
    for (int i = 0; i < 5; i++) lp *= lp;                     // lam^32
    const float* cb = g_carry + b * Sq + s;
    float H = 0.f;
    for (int c = 0; c < chunk; c++)
        H = fmaf(lp, H, cb[(size_t)c * (Bq * Sq)]);
    const size_t base = ((size_t)(b * Tq + chunk * CLEN)) * Sq + s;
    const float* p = g_bu + base;
    __half* ph = g_buh + base;
    float f = lam;
#pragma unroll
    for (int j0 = 0; j0 < CLEN; j0 += 8) {
        float v[8];
#pragma unroll
        for (int u = 0; u < 8; u++) v[u] = p[(size_t)(j0 + u) * Sq];
#pragma unroll
        for (int u = 0; u < 8; u++) { v[u] += f * H; f *= lam; }
#pragma unroll
        for (int u = 0; u < 8; u++) ph[(size_t)(j0 + u) * Sq] = __float2half_rn(v[u]);
    }
}

// ---------------- orchestration ----------------
extern "C" void kernel_launch(void* const* d_in, const int* in_sizes, int n_in,
                              void* d_out, int out_size)
{
    const int*   x      = (const int*)  d_in[0];
    const float* emb    = (const float*)d_in[1];
    const float* pos    = (const float*)d_in[2];
    const float* loglam = (const float*)d_in[3];
    const float* Bw     = (const float*)d_in[4];
    const float* Cw     = (const float*)d_in[5];
    const float* Dp     = (const float*)d_in[6];
    const float* n1w    = (const float*)d_in[7];
    const float* n1b    = (const float*)d_in[8];
    const float* n2w    = (const float*)d_in[9];
    const float* n2b    = (const float*)d_in[10];
    const float* w1     = (const float*)d_in[11];
    const float* w2     = (const float*)d_in[12];
    const float* w3     = (const float*)d_in[13];
    const float* now    = (const float*)d_in[14];
    const float* nob    = (const float*)d_in[15];
    const float* headW  = (const float*)d_in[16];
    const float* headb  = (const float*)d_in[17];
    float* out = (float*)d_out;

    void *ph, *pb, *plh, *pbh, *pfh, *pw;
    cudaGetSymbolAddress(&ph,  g_h);
    cudaGetSymbolAddress(&pb,  g_bu);
    cudaGetSymbolAddress(&plh, g_lnh);
    cudaGetSymbolAddress(&pbh, g_buh);
    cudaGetSymbolAddress(&pfh, g_ffh);
    cudaGetSymbolAddress(&pw,  g_w);
    float*  h   = (float*)ph;
    float*  bu  = (float*)pb;
    __half* lnh = (__half*)plh;
    __half* buh = (__half*)pbh;
    __half* ffh = (__half*)pfh;
    __half* gw  = (__half*)pw;

    cudaFuncSetAttribute((const void*)k_mma<0,64,64>,   cudaFuncAttributeMaxDynamicSharedMemorySize, SMEM6464);
    cudaFuncSetAttribute((const void*)k_mma<2,64,64>,   cudaFuncAttributeMaxDynamicSharedMemorySize, SMEM6464);
    cudaFuncSetAttribute((const void*)k_mma<3,64,128>,  cudaFuncAttributeMaxDynamicSharedMemorySize, SMEM64);
    cudaFuncSetAttribute((const void*)k_mma<1,128,128>, cudaFuncAttributeMaxDynamicSharedMemorySize, SMEM128);
    cudaFuncSetAttribute((const void*)k_mma<4,128,128>, cudaFuncAttributeMaxDynamicSharedMemorySize, SMEM128);

    // ---- weight conversion (once per launch) ----
    k_cvt <<<8000, 256>>>(headW, gw + OFF_HEAD, CNT_HEAD / 8);
    k_cvt <<<256,  256>>>(Bw,    gw + OFF_BW,   CNT_BW / 8);
    k_cvt <<<256,  256>>>(Cw,    gw + OFF_CW,   CNT_BW / 8);
    k_cvt2<<<1368, 256>>>(w1, w2, gw + OFF_W12, CNT_W / 8);
    k_cvt <<<1368, 256>>>(w3,    gw + OFF_W3,   CNT_W / 8);

    const dim3 gBu(BT / 64, Sq / 64);                     // 64 x 4  = 256 CTAs
    const dim3 gC (BT / 64, Dq / 64);                     // 64 x 8  = 512 CTAs
    const dim3 gW12(BT / 128, (2 * DFFq + 127) / 128);    // 32 x 22 = 704 CTAs
    const dim3 gW3(BT / 64, Dq / 128);                    // 64 x 4  = 256 CTAs
    const dim3 gHd(BT / 128, Vq / 128);                   // 32 x 250

    // fused embedding + layer-0 first LN
    k_embed_ln<<<BT, 128>>>(x, emb, pos, n1w, n1b);

    const int lBw = Sq * Dq;
    for (int l = 0; l < Lq; l++) {
        // ---- SSM block ----
        if (l > 0) k_ln<<<BT, 128>>>(h, lnh, n1w + l * Dq, n1b + l * Dq);
        k_mma<0,64,64><<<gBu, 256, SMEM6464>>>(lnh, gw + OFF_BW + (size_t)l * lBw,
                                               bu, nullptr, BT, Sq, Dq, nullptr, nullptr);
        k_scan1 <<<128, 256>>>(loglam + l * Sq);
        k_scan23<<<128, 256>>>(loglam + l * Sq);
        k_mma<2,64,64><<<gC, 256, SMEM6464>>>(buh, gw + OFF_CW + (size_t)l * lBw,
                                              h, nullptr, BT, Dq, Sq, Dp + l * Dq, lnh);
        // ---- SwiGLU block (fused w1+w2 interleaved) ----
        k_ln<<<BT, 128>>>(h, lnh, n2w + l * Dq, n2b + l * Dq);
        k_mma<1,128,128><<<gW12, 256, SMEM128>>>(lnh, gw + OFF_W12 + (size_t)l * 2 * DFFq * Dq,
                                                 nullptr, ffh, BT, 2 * DFFq, Dq, nullptr, nullptr);
        k_mma<3,64,128><<<gW3, 256, SMEM64>>>(ffh, gw + OFF_W3 + (size_t)l * DFFq * Dq,
                                              h, nullptr, BT, Dq, DFFq, nullptr, nullptr);
    }

    // ---- head (128x128 tiles — proven best) ----
    k_ln<<<BT, 128>>>(h, lnh, now, nob);
    k_mma<4,128,128><<<gHd, 256, SMEM128>>>(lnh, gw + OFF_HEAD,
                                            out, nullptr, BT, Vq, Dq, headb, nullptr);
}

// round 17
// speedup vs baseline: 1.0734x; 1.0147x over previous
#include <cuda_runtime.h>
#include <cuda_fp16.h>
#include <math.h>
#include <stdint.h>

#define Bq    2
#define Tq    2048
#define BT    4096
#define Dq    512
#define Sq    256
#define Lq    4
#define DFFq  1368
#define Vq    32000
#define EPSq  1e-5f
#define NCHUNK 128
#define CLEN   16    // Tq / NCHUNK

// ---------------- fp32 scratch ----------------
__device__ __align__(128) float g_h [(size_t)BT * Dq];    // residual stream
__device__ __align__(128) float g_bu[(size_t)BT * Sq];    // Bu (fp32, scan in place)
__device__ __align__(128) float g_carry[NCHUNK * Bq * Sq]; // [chunk][b][s]

// ---------------- fp16 scratch ----------------
__device__ __align__(128) __half g_lnh[(size_t)BT * Dq];   // LN output (A operand)
__device__ __align__(128) __half g_buh[(size_t)BT * Sq];   // scanned h (A operand)
__device__ __align__(128) __half g_ffh[(size_t)BT * DFFq]; // gated product (A operand)

// ---------------- fp16 weight arena ----------------
#define CNT_HEAD (Vq * Dq)
#define CNT_BW   (Lq * Sq * Dq)
#define CNT_W    (Lq * DFFq * Dq)
#define OFF_HEAD 0
#define OFF_BW   (OFF_HEAD + CNT_HEAD)
#define OFF_CW   (OFF_BW + CNT_BW)
#define OFF_W12  (OFF_CW + CNT_BW)         // interleaved w1/w2: 2*CNT_W
#define OFF_W3   (OFF_W12 + 2 * CNT_W)
#define GW_TOTAL (OFF_W3 + CNT_W)
__device__ __align__(128) __half g_w[(size_t)GW_TOTAL];

// ---------------- helpers ----------------
__device__ __forceinline__ uint32_t pack_h2(float x, float y) {
    __half2 h = __floats2half2_rn(x, y);
    return *(uint32_t*)&h;
}
__device__ __forceinline__ void ldm_x4(uint32_t* r, uint32_t addr) {
    asm volatile("ldmatrix.sync.aligned.m8n8.x4.shared.b16 {%0,%1,%2,%3}, [%4];"
                 : "=r"(r[0]), "=r"(r[1]), "=r"(r[2]), "=r"(r[3]) : "r"(addr));
}
__device__ __forceinline__ void mma_f16(float* c, const uint32_t* a, uint32_t b0, uint32_t b1) {
    asm volatile(
        "mma.sync.aligned.m16n8k16.row.col.f32.f16.f16.f32 "
        "{%0,%1,%2,%3}, {%4,%5,%6,%7}, {%8,%9}, {%0,%1,%2,%3};"
        : "+f"(c[0]), "+f"(c[1]), "+f"(c[2]), "+f"(c[3])
        : "r"(a[0]), "r"(a[1]), "r"(a[2]), "r"(a[3]), "r"(b0), "r"(b1));
}
__device__ __forceinline__ void cp16(uint32_t dst, const void* src, int sz) {
    asm volatile("cp.async.cg.shared.global [%0], [%1], 16, %2;"
                 :: "r"(dst), "l"(src), "r"(sz) : "memory");
}
#define CP_COMMIT() asm volatile("cp.async.commit_group;" ::: "memory")
#define CP_WAIT1()  asm volatile("cp.async.wait_group 1;" ::: "memory")
#define CP_WAIT0()  asm volatile("cp.async.wait_group 0;" ::: "memory")

// ---------------- weight converts (fp32 -> fp16) ----------------
__global__ void k_cvt(const float* __restrict__ s, __half* __restrict__ d, int n8)
{
    const int i = blockIdx.x * blockDim.x + threadIdx.x;
    if (i >= n8) return;
    float4 a = ((const float4*)s)[2 * i];
    float4 b = ((const float4*)s)[2 * i + 1];
    uint4 o;
    o.x = pack_h2(a.x, a.y); o.y = pack_h2(a.z, a.w);
    o.z = pack_h2(b.x, b.y); o.w = pack_h2(b.z, b.w);
    ((uint4*)d)[i] = o;
}

// interleave w1/w2 rows per layer: dst row (l, 2f) = w1[l,f], (l, 2f+1) = w2[l,f]
__global__ void k_cvt2(const float* __restrict__ w1, const float* __restrict__ w2,
                       __half* __restrict__ d, int n8)
{
    const int i = blockIdx.x * blockDim.x + threadIdx.x;
    if (i >= n8) return;
    const int fg  = i >> 6;
    const int off = (i & 63) * 8;
    const int l   = fg / DFFq;
    const int f   = fg - l * DFFq;
    const float4* s1 = (const float4*)(w1 + (size_t)fg * Dq + off);
    const float4* s2 = (const float4*)(w2 + (size_t)fg * Dq + off);
    __half* dst = d + ((size_t)l * 2 * DFFq + 2 * f) * Dq + off;
    float4 a = s1[0], b = s1[1];
    uint4 o;
    o.x = pack_h2(a.x, a.y); o.y = pack_h2(a.z, a.w);
    o.z = pack_h2(b.x, b.y); o.w = pack_h2(b.z, b.w);
    *(uint4*)dst = o;
    a = s2[0]; b = s2[1];
    o.x = pack_h2(a.x, a.y); o.y = pack_h2(a.z, a.w);
    o.z = pack_h2(b.x, b.y); o.w = pack_h2(b.z, b.w);
    *(uint4*)(dst + Dq) = o;
}

// ---------------- LN core (128 threads, one row of 512) ----------------
__device__ __forceinline__ void ln_row(const float4 v, const float* w, const float* b,
                                       __half* out_row, int c)
{
    float s  = v.x + v.y + v.z + v.w;
    float ss = v.x*v.x + v.y*v.y + v.z*v.z + v.w*v.w;
#pragma unroll
    for (int o = 16; o > 0; o >>= 1) {
        s  += __shfl_xor_sync(0xffffffffu, s,  o);
        ss += __shfl_xor_sync(0xffffffffu, ss, o);
    }
    __shared__ float sm[10];
    const int wid = c >> 5;
    if ((c & 31) == 0) { sm[wid] = s; sm[4 + wid] = ss; }
    __syncthreads();
    if (c == 0) {
        float S1 = sm[0] + sm[1] + sm[2] + sm[3];
        float S2 = sm[4] + sm[5] + sm[6] + sm[7];
        float mu  = S1 * (1.0f / Dq);
        float var = S2 * (1.0f / Dq) - mu * mu;
        sm[8] = mu;
        sm[9] = rsqrtf(var + EPSq);
    }
    __syncthreads();
    const float mu = sm[8], rs = sm[9];
    const float4 wv = ((const float4*)w)[c];
    const float4 bv = ((const float4*)b)[c];
    uint2 o;
    o.x = pack_h2((v.x - mu) * rs * wv.x + bv.x, (v.y - mu) * rs * wv.y + bv.y);
    o.y = pack_h2((v.z - mu) * rs * wv.z + bv.z, (v.w - mu) * rs * wv.w + bv.w);
    ((uint2*)out_row)[c] = o;
}

// ---------------- fused embedding + first LN ----------------
__global__ void k_embed_ln(const int* __restrict__ x, const float* __restrict__ emb,
                           const float* __restrict__ pos,
                           const float* __restrict__ w, const float* __restrict__ b)
{
    const int row = blockIdx.x;
    const int t   = row & (Tq - 1);
    const int tok = x[row];
    const int c   = threadIdx.x;
    const float4 e = ((const float4*)(emb + (size_t)tok * Dq))[c];
    const float4 p = ((const float4*)(pos + (size_t)t * Dq))[c];
    const float4 v = make_float4(e.x + p.x, e.y + p.y, e.z + p.z, e.w + p.w);
    ((float4*)(g_h + (size_t)row * Dq))[c] = v;
    ln_row(v, w, b, g_lnh + (size_t)row * Dq, c);
}

// ---------------- layernorm: fp32 in -> fp16 out ----------------
__global__ void k_ln(const float* __restrict__ in, __half* __restrict__ out,
                     const float* __restrict__ w, const float* __restrict__ b)
{
    const int row = blockIdx.x;
    const int c = threadIdx.x;
    const float4 v = ((const float4*)(in + (size_t)row * Dq))[c];
    ln_row(v, w, b, out + (size_t)row * Dq, c);
}

// =================== fp16 mma GEMM: C = A[M,K]*B[N,K]^T (half inputs) ===========
// CTA tile MT x NT, BK=64, 3-stage cp.async, 256 threads = 8 warps (2m x 4n).
// Warp tile (MT/2) x (NT/4). Single barrier per chunk. Tail drains all groups.
// MODE 0: C = acc                              (fp32 out)
// MODE 1: fused SwiGLU, interleaved N=2*DFF:   Ch[m][n>>1] = silu(g)*v
// MODE 2: C = C + acc + aux1[n]*aux2h[m,n]     (SSM residual)
// MODE 3: C = C + acc                          (FFN residual)
// MODE 4: C = acc + aux1[n]   (head bias; streaming .cs stores, never re-read)
template<int MODE, int MT, int NT>
__global__ void __launch_bounds__(256, 2)
k_mma(const __half* __restrict__ A, const __half* __restrict__ Bm,
      float* __restrict__ C, __half* __restrict__ Ch, int M, int N, int K,
      const float* __restrict__ aux1, const __half* __restrict__ aux2)
{
    constexpr int MI   = MT / 32;        // A staging iters / m16 frags per warp
    constexpr int NI   = NT / 32;        // n8 frags per warp
    constexpr int WMR  = MT / 2;         // warp m rows
    constexpr int WNR  = NT / 4;         // warp n cols
    constexpr uint32_t ASTG = (uint32_t)MT * 128;
    constexpr uint32_t BSTG = (uint32_t)NT * 128;
    constexpr uint32_t BOFF = 3 * ASTG;

    extern __shared__ char smem[];
    const uint32_t sb = (uint32_t)__cvta_generic_to_shared(smem);

    const int tid  = threadIdx.x;
    const int wid  = tid >> 5;
    const int lane = tid & 31;
    const int gid  = lane >> 2;
    const int tig  = lane & 3;
    const int hi   = lane >> 4;
    const int lrow = lane & 15;
    const int rswz = lrow & 7;
    const int wm   = wid & 1;
    const int wn   = wid >> 1;
    const int bm   = blockIdx.x * MT;
    const int bn   = blockIdx.y * NT;

    const int r0  = tid >> 3;
    const int c16 = tid & 7;
    const uint32_t swz16 = (uint32_t)((c16 ^ (r0 & 7)) * 16);
    const __half* Asrc = A  + (size_t)(bm + r0) * K + c16 * 8;
    const __half* Bsrc = Bm + (size_t)(bn + r0) * K + c16 * 8;

    float acc[MI][NI][4];
#pragma unroll
    for (int i = 0; i < MI; i++)
#pragma unroll
        for (int j = 0; j < NI; j++)
#pragma unroll
            for (int q = 0; q < 4; q++) acc[i][j][q] = 0.f;

    const int nk = (K + 63) >> 6;

    auto issue = [&](int kc) {
        const uint32_t sta = (uint32_t)(kc % 3) * ASTG;
        const uint32_t stb = BOFF + (uint32_t)(kc % 3) * BSTG;
        const int k0 = kc << 6;
        const int ksz = (k0 + c16 * 8 + 8 <= K) ? 16 : 0;
#pragma unroll
        for (int i = 0; i < MI; i++) {
            const uint32_t dof = (uint32_t)((i * 32 + r0) * 128) + swz16;
            cp16(sb + sta + dof, Asrc + (size_t)(i * 32) * K + k0, ksz);
        }
#pragma unroll
        for (int i = 0; i < NI; i++) {
            const uint32_t dof = (uint32_t)((i * 32 + r0) * 128) + swz16;
            const int bsz = ((bn + i * 32 + r0) < N) ? ksz : 0;
            cp16(sb + stb + dof, Bsrc + (size_t)(i * 32) * K + k0, bsz);
        }
        CP_COMMIT();
    };

    issue(0);
    issue(1);

#pragma unroll 1
    for (int kch = 0; kch < nk; kch++) {
        if (kch + 1 < nk) { CP_WAIT1(); } else { CP_WAIT0(); }   // tail drains all
        __syncthreads();            // single barrier per chunk
        if (kch + 2 < nk) issue(kch + 2);

        const uint32_t arow = sb + (uint32_t)(kch % 3) * ASTG
                              + (uint32_t)((wm * WMR + lrow) * 128);
        const uint32_t brow = sb + BOFF + (uint32_t)(kch % 3) * BSTG
                              + (uint32_t)((wn * WNR + lrow) * 128);
#pragma unroll
        for (int ks = 0; ks < 4; ks++) {
            const uint32_t csw = (uint32_t)(((ks * 2 + hi) ^ rswz) * 16);
            uint32_t afr[MI][4];
#pragma unroll
            for (int mi = 0; mi < MI; mi++)
                ldm_x4(afr[mi], arow + (uint32_t)(mi * 16 * 128) + csw);
            uint32_t bfr[NI / 2][4];
#pragma unroll
            for (int nj = 0; nj < NI / 2; nj++)
                ldm_x4(bfr[nj], brow + (uint32_t)(nj * 16 * 128) + csw);
#pragma unroll
            for (int mi = 0; mi < MI; mi++)
#pragma unroll
                for (int ni = 0; ni < NI; ni++) {
                    const int nj = ni >> 1, h = ni & 1;
                    mma_f16(acc[mi][ni], afr[mi], bfr[nj][h], bfr[nj][h + 2]);
                }
        }
    }

    // ---- epilogue ----
#pragma unroll
    for (int mi = 0; mi < MI; mi++) {
        const int r0m = bm + wm * WMR + mi * 16 + gid;
#pragma unroll
        for (int half = 0; half < 2; half++) {
            const int m = r0m + half * 8;
            const size_t rowoff = (size_t)m * N;
#pragma unroll
            for (int ni = 0; ni < NI; ni++) {
                const int n0 = bn + wn * WNR + ni * 8;
                if (n0 >= N) continue;
                const int n = n0 + tig * 2;
                float2 rv;
                rv.x = acc[mi][ni][half * 2 + 0];
                rv.y = acc[mi][ni][half * 2 + 1];
                if (MODE == 0) {
                    *(float2*)(C + rowoff + n) = rv;
                } else if (MODE == 1) {
                    const int f = n >> 1;
                    float r = rv.y * rv.x / (1.f + __expf(-rv.x));
                    Ch[(size_t)m * DFFq + f] = __float2half_rn(r);
                } else if (MODE == 2) {
                    float2* cp = (float2*)(C + rowoff + n);
                    float2 c  = *cp;
                    float2 dp = *(const float2*)(aux1 + n);
                    float2 u  = __half22float2(*(const __half2*)(aux2 + rowoff + n));
                    rv.x += c.x + dp.x * u.x;
                    rv.y += c.y + dp.y * u.y;
                    *cp = rv;
                } else if (MODE == 3) {
                    float2* cp = (float2*)(C + rowoff + n);
                    float2 c = *cp;
                    rv.x += c.x; rv.y += c.y;
                    *cp = rv;
                } else {
                    float2 bb = *(const float2*)(aux1 + n);
                    rv.x += bb.x; rv.y += bb.y;
                    __stcs((float2*)(C + rowoff + n), rv);   // streaming: protect L2
                }
            }
        }
    }
}

#define SMEM64   73728    // MT=64,  NT=128
#define SMEM128  98304    // MT=128, NT=128

// ---------------- SSM scan phase 1: local chunk scans + carries ----------------
__global__ void k_scan1(const float* __restrict__ loglam)
{
    const int idx   = blockIdx.x * blockDim.x + threadIdx.x;  // 0..65535
    const int s     = idx & (Sq - 1);
    const int b     = (idx >> 8) & 1;
    const int chunk = idx >> 9;
    const float lam = 1.f / (1.f + expf(-loglam[s]));
    float* p = g_bu + ((size_t)(b * Tq + chunk * CLEN)) * Sq + s;
    float h = 0.f;
    float buf[4];
#pragma unroll
    for (int j = 0; j < 4; j++) buf[j] = p[(size_t)j * Sq];
#pragma unroll
    for (int j0 = 0; j0 < CLEN; j0 += 4) {
        float c0 = buf[0], c1 = buf[1], c2 = buf[2], c3 = buf[3];
        if (j0 + 4 < CLEN) {
#pragma unroll
            for (int j = 0; j < 4; j++) buf[j] = p[(size_t)(j0 + 4 + j) * Sq];
        }
        h = fmaf(lam, h, c0); p[(size_t)(j0 + 0) * Sq] = h;
        h = fmaf(lam, h, c1); p[(size_t)(j0 + 1) * Sq] = h;
        h = fmaf(lam, h, c2); p[(size_t)(j0 + 2) * Sq] = h;
        h = fmaf(lam, h, c3); p[(size_t)(j0 + 3) * Sq] = h;
    }
    g_carry[(size_t)chunk * (Bq * Sq) + b * Sq + s] = h;      // [chunk][b][s]
}

// ---------------- scan phase 2+3 fused: local carry-prefix, fixup, half out ----
__global__ void k_scan23(const float* __restrict__ loglam)
{
    const int idx   = blockIdx.x * blockDim.x + threadIdx.x;
    const int s     = idx & (Sq - 1);
    const int b     = (idx >> 8) & 1;
    const int chunk = idx >> 9;                               // warp-uniform
    const float lam = 1.f / (1.f + expf(-loglam[s]));
    float lp = lam;
#pragma unroll
    for (int i = 0; i < 4; i++) lp *= lp;                     // lam^16 (CLEN=16)
    const float* cb = g_carry + b * Sq + s;
    float H = 0.f;
    for (int c = 0; c < chunk; c++)
        H = fmaf(lp, H, cb[(size_t)c * (Bq * Sq)]);
    const size_t base = ((size_t)(b * Tq + chunk * CLEN)) * Sq + s;
    const float* p = g_bu + base;
    __half* ph = g_buh + base;
    float f = lam;
#pragma unroll
    for (int j0 = 0; j0 < CLEN; j0 += 8) {
        float v[8];
#pragma unroll
        for (int u = 0; u < 8; u++) v[u] = p[(size_t)(j0 + u) * Sq];
#pragma unroll
        for (int u = 0; u < 8; u++) { v[u] += f * H; f *= lam; }
#pragma unroll
        for (int u = 0; u < 8; u++) ph[(size_t)(j0 + u) * Sq] = __float2half_rn(v[u]);
    }
}

// ---------------- orchestration ----------------
extern "C" void kernel_launch(void* const* d_in, const int* in_sizes, int n_in,
                              void* d_out, int out_size)
{
    const int*   x      = (const int*)  d_in[0];
    const float* emb    = (const float*)d_in[1];
    const float* pos    = (const float*)d_in[2];
    const float* loglam = (const float*)d_in[3];
    const float* Bw     = (const float*)d_in[4];
    const float* Cw     = (const float*)d_in[5];
    const float* Dp     = (const float*)d_in[6];
    const float* n1w    = (const float*)d_in[7];
    const float* n1b    = (const float*)d_in[8];
    const float* n2w    = (const float*)d_in[9];
    const float* n2b    = (const float*)d_in[10];
    const float* w1     = (const float*)d_in[11];
    const float* w2     = (const float*)d_in[12];
    const float* w3     = (const float*)d_in[13];
    const float* now    = (const float*)d_in[14];
    const float* nob    = (const float*)d_in[15];
    const float* headW  = (const float*)d_in[16];
    const float* headb  = (const float*)d_in[17];
    float* out = (float*)d_out;

    void *ph, *pb, *plh, *pbh, *pfh, *pw;
    cudaGetSymbolAddress(&ph,  g_h);
    cudaGetSymbolAddress(&pb,  g_bu);
    cudaGetSymbolAddress(&plh, g_lnh);
    cudaGetSymbolAddress(&pbh, g_buh);
    cudaGetSymbolAddress(&pfh, g_ffh);
    cudaGetSymbolAddress(&pw,  g_w);
    float*  h   = (float*)ph;
    float*  bu  = (float*)pb;
    __half* lnh = (__half*)plh;
    __half* buh = (__half*)pbh;
    __half* ffh = (__half*)pfh;
    __half* gw  = (__half*)pw;

    cudaFuncSetAttribute((const void*)k_mma<0,64,128>,  cudaFuncAttributeMaxDynamicSharedMemorySize, SMEM64);
    cudaFuncSetAttribute((const void*)k_mma<2,64,128>,  cudaFuncAttributeMaxDynamicSharedMemorySize, SMEM64);
    cudaFuncSetAttribute((const void*)k_mma<3,64,128>,  cudaFuncAttributeMaxDynamicSharedMemorySize, SMEM64);
    cudaFuncSetAttribute((const void*)k_mma<1,128,128>, cudaFuncAttributeMaxDynamicSharedMemorySize, SMEM128);
    cudaFuncSetAttribute((const void*)k_mma<4,128,128>, cudaFuncAttributeMaxDynamicSharedMemorySize, SMEM128);

    // ---- weight conversion (once per launch) ----
    k_cvt <<<8000, 256>>>(headW, gw + OFF_HEAD, CNT_HEAD / 8);
    k_cvt <<<256,  256>>>(Bw,    gw + OFF_BW,   CNT_BW / 8);
    k_cvt <<<256,  256>>>(Cw,    gw + OFF_CW,   CNT_BW / 8);
    k_cvt2<<<1368, 256>>>(w1, w2, gw + OFF_W12, CNT_W / 8);
    k_cvt <<<1368, 256>>>(w3,    gw + OFF_W3,   CNT_W / 8);

    const dim3 gBu(BT / 64, Sq / 128);                    // 64 x 2  (R13-proven)
    const dim3 gC (BT / 64, Dq / 128);                    // 64 x 4
    const dim3 gW12(BT / 128, (2 * DFFq + 127) / 128);    // 32 x 22
    const dim3 gW3(BT / 64, Dq / 128);                    // 64 x 4
    const dim3 gHd(BT / 128, Vq / 128);                   // 32 x 250

    // fused embedding + layer-0 first LN
    k_embed_ln<<<BT, 128>>>(x, emb, pos, n1w, n1b);

    const int lBw = Sq * Dq;
    for (int l = 0; l < Lq; l++) {
        // ---- SSM block ----
        if (l > 0) k_ln<<<BT, 128>>>(h, lnh, n1w + l * Dq, n1b + l * Dq);
        k_mma<0,64,128><<<gBu, 256, SMEM64>>>(lnh, gw + OFF_BW + (size_t)l * lBw,
                                              bu, nullptr, BT, Sq, Dq, nullptr, nullptr);
        k_scan1 <<<256, 256>>>(loglam + l * Sq);
        k_scan23<<<256, 256>>>(loglam + l * Sq);
        k_mma<2,64,128><<<gC, 256, SMEM64>>>(buh, gw + OFF_CW + (size_t)l * lBw,
                                             h, nullptr, BT, Dq, Sq, Dp + l * Dq, lnh);
        // ---- SwiGLU block (fused w1+w2 interleaved) ----
        k_ln<<<BT, 128>>>(h, lnh, n2w + l * Dq, n2b + l * Dq);
        k_mma<1,128,128><<<gW12, 256, SMEM128>>>(lnh, gw + OFF_W12 + (size_t)l * 2 * DFFq * Dq,
                                                 nullptr, ffh, BT, 2 * DFFq, Dq, nullptr, nullptr);
        k_mma<3,64,128><<<gW3, 256, SMEM64>>>(ffh, gw + OFF_W3 + (size_t)l * DFFq * Dq,
                                              h, nullptr, BT, Dq, DFFq, nullptr, nullptr);
    }

    // ---- head (128x128 tiles — proven best; streaming stores) ----
    k_ln<<<BT, 128>>>(h, lnh, now, nob);
    k_mma<4,128,128><<<gHd, 256, SMEM128>>>(lnh, gw + OFF_HEAD,
                                            out, nullptr, BT, Vq, Dq, headb, nullptr);
}